// round 1
// baseline (speedup 1.0000x reference)
#include <cuda_runtime.h>

// ============================================================================
// Compile-time Clebsch-Gordan machinery (Condon-Shortley, real SH basis),
// faithful to the reference's _cg_complex / _u / _cg_real.
// All constexpr so CG values become immediate constants in SASS; zero entries
// are dead-code-eliminated via `if constexpr`.
// ============================================================================
namespace cgc {

__host__ __device__ constexpr double cfact(int n) {
    double r = 1.0;
    for (int i = 2; i <= n; ++i) r *= (double)i;
    return r;
}

__host__ __device__ constexpr double csqrt(double x) {
    if (x <= 0.0) return 0.0;
    double r = x > 1.0 ? x : 1.0;
    for (int i = 0; i < 200; ++i) {
        double nr = 0.5 * (r + x / r);
        if (nr == r) break;
        r = nr;
    }
    return r;
}

// <l3 m3 | l1 m1 l2 m2>, m3 = m1 + m2
__host__ __device__ constexpr double cg_complex(int l1, int l2, int l3, int m1, int m2) {
    int m3 = m1 + m2;
    if (m3 < -l3 || m3 > l3) return 0.0;
    double pre = csqrt((2 * l3 + 1) * cfact(l1 + l2 - l3) * cfact(l1 - l2 + l3) *
                       cfact(-l1 + l2 + l3) / cfact(l1 + l2 + l3 + 1));
    pre *= csqrt(cfact(l3 + m3) * cfact(l3 - m3) * cfact(l1 - m1) * cfact(l1 + m1) *
                 cfact(l2 - m2) * cfact(l2 + m2));
    double s = 0.0;
    for (int k = 0; k <= l1 + l2 - l3; ++k) {
        int d1 = k, d2 = l1 + l2 - l3 - k, d3 = l1 - m1 - k, d4 = l2 + m2 - k;
        int d5 = l3 - l2 + m1 + k, d6 = l3 - l1 - m2 + k;
        if (d1 < 0 || d2 < 0 || d3 < 0 || d4 < 0 || d5 < 0 || d6 < 0) continue;
        double den = cfact(d1) * cfact(d2) * cfact(d3) * cfact(d4) * cfact(d5) * cfact(d6);
        s += ((k & 1) ? -1.0 : 1.0) / den;
    }
    return pre * s;
}

// complex->real basis change U(l); row a = l + m_real, col i = l + m_complex
__host__ __device__ constexpr double u_re(int l, int a, int i) {
    int mr = a - l, mc = i - l;
    double inv = 1.0 / csqrt(2.0);
    if (mr == 0) return (mc == 0) ? 1.0 : 0.0;
    if (mr > 0) {
        if (mc == mr)  return ((mr & 1) ? -inv : inv);   // (-1)^m / sqrt(2)
        if (mc == -mr) return inv;                       // 1 / sqrt(2)
    }
    return 0.0;
}
__host__ __device__ constexpr double u_im(int l, int a, int i) {
    int mr = a - l, mc = i - l;
    double inv = 1.0 / csqrt(2.0);
    if (mr < 0) {
        int m = -mr;
        if (mc == -m) return inv;                        // i / sqrt(2)
        if (mc == m)  return ((m & 1) ? inv : -inv);     // -i (-1)^m / sqrt(2)
    }
    return 0.0;
}

// real-basis CG; purely real for even l1+l2+l3, purely imaginary for odd
// (matches reference's magnitude-based real/imag selection)
__host__ __device__ constexpr double cg_real(int l1, int l2, int l3, int a, int b, int c) {
    double re = 0.0, im = 0.0;
    for (int i = 0; i < 2 * l1 + 1; ++i) {
        for (int j = 0; j < 2 * l2 + 1; ++j) {
            int k = (i - l1) + (j - l2) + l3;   // m3 = m1 + m2
            if (k < 0 || k > 2 * l3) continue;
            double Cv = cg_complex(l1, l2, l3, i - l1, j - l2);
            if (Cv == 0.0) continue;
            double u1r = u_re(l1, a, i), u1i = u_im(l1, a, i);
            double u2r = u_re(l2, b, j), u2i = u_im(l2, b, j);
            double u3r = u_re(l3, c, k), u3i = -u_im(l3, c, k);  // conj
            double pr = u1r * u2r - u1i * u2i;
            double pi = u1r * u2i + u1i * u2r;
            double rr = pr * u3r - pi * u3i;
            double ri = pr * u3i + pi * u3r;
            re += rr * Cv;
            im += ri * Cv;
        }
    }
    return (((l1 + l2 + l3) & 1) ? im : re);
}

__host__ __device__ constexpr bool pair_used(int l1, int l2, int l3, int i, int j) {
    for (int k = 0; k < 2 * l3 + 1; ++k) {
        double v = cg_real(l1, l2, l3, i, j, k);
        if (v > 1e-9 || v < -1e-9) return true;
    }
    return false;
}

}  // namespace cgc

// ============================================================================
// Fully-unrolled sparse contraction via template recursion.
// For L1==L2 we iterate i<=j with off-diagonal terms doubled (cg symmetric in
// (i,j) for even LO; odd-LO diagonal couplings are skipped at the call sites
// because x (x) x kills the antisymmetric part exactly).
// ============================================================================
template <int L1, int L2, int LO, int I, int J, int K>
struct TermK {
    __device__ static __forceinline__ void run(float q, float* o) {
        {
            constexpr double vd =
                cgc::cg_real(L1, L2, LO, I, J, K) * ((L1 == L2 && I < J) ? 2.0 : 1.0);
            constexpr float V = (float)vd;
            if constexpr (V > 1e-7f || V < -1e-7f) {
                o[K] = fmaf(V, q, o[K]);
            }
        }
        if constexpr (K + 1 <= 2 * LO) TermK<L1, L2, LO, I, J, K + 1>::run(q, o);
    }
};

template <int L1, int L2, int LO, int I, int J>
struct PairLoop {
    __device__ static __forceinline__ void run(const float* xa, const float* xb,
                                               float s, float* o) {
        if constexpr (cgc::pair_used(L1, L2, LO, I, J)) {
            float q = (xa[I] * xb[J]) * s;
            TermK<L1, L2, LO, I, J, 0>::run(q, o);
        }
        if constexpr (J < 2 * L2) {
            PairLoop<L1, L2, LO, I, J + 1>::run(xa, xb, s, o);
        } else if constexpr (I < 2 * L1) {
            PairLoop<L1, L2, LO, I + 1, (L1 == L2 ? I + 1 : 0)>::run(xa, xb, s, o);
        }
    }
};

// ============================================================================
// Kernel: one thread per (batch row, channel). 128 channels = 4 warps wide,
// perfectly coalesced 128B transactions on both loads and stores.
//
// Input  layout: x[b, off_l + m*128 + c], offs {0, 128, 512},  DIM_IN  = 1152
// Output layout: out[b, off_lo + k*128 + c], offs {0,128,512,1152,2048}, 3200
//
// Mix-coefficient rows (coupling enumeration lo-major, l1-major, l2-minor):
//  0:(0|0,0) 1:(0|1,1) 2:(0|2,2) 3:(1|0,1) 4:(1|1,0) 5:(1|1,1)* 6:(1|1,2)
//  7:(1|2,1) 8:(1|2,2)* 9:(2|0,2) 10:(2|1,1) 11:(2|1,2) 12:(2|2,0)
//  13:(2|2,1) 14:(2|2,2) 15:(3|1,2) 16:(3|2,1) 17:(3|2,2)* 18:(4|2,2)
//  (* = antisymmetric under x(x)x -> exactly zero, dropped)
// Swap-merged pairs use cg(l2,l1,lo)[j,i,k] = (-1)^(l1+l2+lo) cg(l1,l2,lo)[i,j,k]:
//  rows 3+4 -> +, 6+7 -> +, 9+12 -> +, 11-13 -> -, 15+16 -> +
// ============================================================================
__global__ void __launch_bounds__(256) selfmix_kernel(
    const float* __restrict__ x, const float* __restrict__ keep,
    const float* __restrict__ mix, float* __restrict__ out, int B) {
    const int c = threadIdx.x & 127;
    const int b = blockIdx.x * 2 + (threadIdx.x >> 7);
    if (b >= B) return;

    const float* xb = x + (long long)b * 1152;
    float x0[1], x1[3], x2[5];
    x0[0] = xb[c];
#pragma unroll
    for (int m = 0; m < 3; ++m) x1[m] = xb[128 + m * 128 + c];
#pragma unroll
    for (int m = 0; m < 5; ++m) x2[m] = xb[512 + m * 128 + c];

    // keep (skip) path initializes the l<=2 output accumulators
    float o0[1], o1[3], o2[5], o3[7], o4[9];
    o0[0] = keep[c] * x0[0];
    {
        float k1 = keep[128 + c];
#pragma unroll
        for (int m = 0; m < 3; ++m) o1[m] = k1 * x1[m];
    }
    {
        float k2 = keep[256 + c];
#pragma unroll
        for (int m = 0; m < 5; ++m) o2[m] = k2 * x2[m];
    }
#pragma unroll
    for (int m = 0; m < 7; ++m) o3[m] = 0.f;
#pragma unroll
    for (int m = 0; m < 9; ++m) o4[m] = 0.f;

    // merged per-channel coefficients (0.5 * s folded in)
    const float s000 = 0.5f * mix[0 * 128 + c];
    const float s110 = 0.5f * mix[1 * 128 + c];
    const float s220 = 0.5f * mix[2 * 128 + c];
    const float s011 = 0.5f * (mix[3 * 128 + c] + mix[4 * 128 + c]);
    const float s121 = 0.5f * (mix[6 * 128 + c] + mix[7 * 128 + c]);
    const float s022 = 0.5f * (mix[9 * 128 + c] + mix[12 * 128 + c]);
    const float s112 = 0.5f * mix[10 * 128 + c];
    const float s122 = 0.5f * (mix[11 * 128 + c] - mix[13 * 128 + c]);
    const float s222 = 0.5f * mix[14 * 128 + c];
    const float s123 = 0.5f * (mix[15 * 128 + c] + mix[16 * 128 + c]);
    const float s224 = 0.5f * mix[18 * 128 + c];

    // lout = 0
    PairLoop<0, 0, 0, 0, 0>::run(x0, x0, s000, o0);
    PairLoop<1, 1, 0, 0, 0>::run(x1, x1, s110, o0);
    PairLoop<2, 2, 0, 0, 0>::run(x2, x2, s220, o0);
    // lout = 1
    PairLoop<0, 1, 1, 0, 0>::run(x0, x1, s011, o1);
    PairLoop<1, 2, 1, 0, 0>::run(x1, x2, s121, o1);
    // lout = 2
    PairLoop<0, 2, 2, 0, 0>::run(x0, x2, s022, o2);
    PairLoop<1, 1, 2, 0, 0>::run(x1, x1, s112, o2);
    PairLoop<1, 2, 2, 0, 0>::run(x1, x2, s122, o2);
    PairLoop<2, 2, 2, 0, 0>::run(x2, x2, s222, o2);
    // lout = 3
    PairLoop<1, 2, 3, 0, 0>::run(x1, x2, s123, o3);
    // lout = 4
    PairLoop<2, 2, 4, 0, 0>::run(x2, x2, s224, o4);

    float* ob = out + (long long)b * 3200;
    ob[c] = o0[0];
#pragma unroll
    for (int m = 0; m < 3; ++m) ob[128 + m * 128 + c] = o1[m];
#pragma unroll
    for (int m = 0; m < 5; ++m) ob[512 + m * 128 + c] = o2[m];
#pragma unroll
    for (int m = 0; m < 7; ++m) ob[1152 + m * 128 + c] = o3[m];
#pragma unroll
    for (int m = 0; m < 9; ++m) ob[2048 + m * 128 + c] = o4[m];
}

extern "C" void kernel_launch(void* const* d_in, const int* in_sizes, int n_in,
                              void* d_out, int out_size) {
    // Identify inputs robustly by element count: x is the big one,
    // keep_coeff has 384 elements, mix_coeff has 2432.
    const float* x = nullptr;
    const float* keep = nullptr;
    const float* mix = nullptr;
    int bx = 0;
    for (int i = 0; i < n_in; ++i) {
        if (in_sizes[i] == 384) keep = (const float*)d_in[i];
        else if (in_sizes[i] == 2432) mix = (const float*)d_in[i];
        else { x = (const float*)d_in[i]; bx = in_sizes[i]; }
    }
    float* out = (float*)d_out;
    int B = bx / 1152;
    int blocks = (B + 1) / 2;  // 2 rows per 256-thread block (128 channels wide)
    selfmix_kernel<<<blocks, 256>>>(x, keep, mix, out, B);
}